// round 7
// baseline (speedup 1.0000x reference)
#include <cuda_runtime.h>

#define K2T  49
#define NH   3
#define DIMC 96
#define PSTR 52
#define MAXW 128

// ---- global scratch ----
__device__ float gGwT[DIMC * DIMC];              // gGwT[he][c] = Gw[c*96+he]
__device__ float gBias[NH * K2T * K2T];          // gBias[h][i*49+j] = rpb[rp[ij]*3+h]
__device__ float Pg[MAXW * 288 * PSTR];          // per window: rows 0..95 Q(scaled), 96..191 K, 192..287 Y^T
__device__ float VTg[MAXW * DIMC * PSTR];        // VTg[w][he][i]
__device__ float bottg[MAXW * 64];

__device__ __forceinline__ float dot4(float4 a, float4 b, float acc) {
    acc = fmaf(a.x, b.x, acc);
    acc = fmaf(a.y, b.y, acc);
    acc = fmaf(a.z, b.z, acc);
    acc = fmaf(a.w, b.w, acc);
    return acc;
}
__device__ __forceinline__ float fcomp(float4 v, int k) {
    return k == 0 ? v.x : (k == 1 ? v.y : (k == 2 ? v.z : v.w));
}
// packed 2xfp32 fma (Blackwell FFMA2; same rounding as scalar fmaf)
__device__ __forceinline__ float2 ffma2(float2 a, float2 b, float2 c) {
    float2 d;
    asm("{\n\t"
        ".reg .b64 ra, rb, rc, rd;\n\t"
        "mov.b64 ra, {%2,%3};\n\t"
        "mov.b64 rb, {%4,%5};\n\t"
        "mov.b64 rc, {%6,%7};\n\t"
        "fma.rn.f32x2 rd, ra, rb, rc;\n\t"
        "mov.b64 {%0,%1}, rd;\n\t"
        "}"
        : "=f"(d.x), "=f"(d.y)
        : "f"(a.x), "f"(a.y), "f"(b.x), "f"(b.y), "f"(c.x), "f"(c.y));
    return d;
}

// ================= prep: transpose Gw, gather rpb =================
__global__ void prep_kernel(const float* __restrict__ Gw,
                            const float* __restrict__ rpb,
                            const int*   __restrict__ rp)
{
    int t = blockIdx.x * blockDim.x + threadIdx.x;
    if (t < DIMC * DIMC) {
        int c = t / DIMC, he = t - c * DIMC;
        gGwT[he * DIMC + c] = Gw[t];
    }
    if (t < NH * K2T * K2T) {
        int h = t / (K2T * K2T), ij = t - h * (K2T * K2T);
        gBias[t] = rpb[rp[ij] * NH + h];
    }
}

// ================= K1: fused Q/K/Y projection + bott =================
// grid = 2*BW (2 CTAs per window, 144 output rows each), block = 256
__global__ __launch_bounds__(256, 2)
void k1_proj(const float* __restrict__ x,    const float* __restrict__ qk_w,
             const float* __restrict__ qk_b, const float* __restrict__ botw,
             const float* __restrict__ botb)
{
    __shared__ float xT[DIMC * PSTR];   // xT[c][j], cols 49..51 zero
    const int bid  = blockIdx.x;
    const int w    = bid >> 1;
    const int half = bid & 1;
    const int tid  = threadIdx.x;
    const float* xg = x + (size_t)w * (K2T * DIMC);

    for (int i = tid; i < K2T * DIMC; i += 256) {
        int j = i / DIMC, c = i - j * DIMC;
        xT[c * PSTR + j] = xg[i];
    }
    for (int i = tid; i < DIMC * 3; i += 256) {
        int c = i / 3, j = K2T + (i % 3);
        xT[c * PSTR + j] = 0.f;
    }
    if (half == 0 && tid < 64) {
        float acc = 0.f;
        if (tid < K2T) {
            const float4* xr  = (const float4*)(xg + tid * DIMC);
            const float4* bw4 = (const float4*)botw;
            acc = botb[0];
            #pragma unroll 6
            for (int c4 = 0; c4 < 24; c4++) acc = dot4(xr[c4], bw4[c4], acc);
        }
        bottg[w * 64 + tid] = acc;
    }
    __syncthreads();

    const float SCALE = 0.17677669529663687f;  // 32^-0.5
    if (tid < 234) {                           // 18 r-tiles x 13 j-tiles
        const int rt = tid / 13;
        const int jt = tid - rt * 13;
        const int r0 = half * 144 + rt * 8;
        const int j0 = jt * 4;
        const bool isQK = (r0 < 192);
        const float* wbase = isQK ? (qk_w + r0 * 96) : (gGwT + (r0 - 192) * 96);

        float2 acc[8][2];
        #pragma unroll
        for (int a = 0; a < 8; a++) {
            float bv = isQK ? qk_b[r0 + a] : 0.f;
            acc[a][0] = make_float2(bv, bv);
            acc[a][1] = make_float2(bv, bv);
        }

        #pragma unroll 2
        for (int c0 = 0; c0 < DIMC; c0 += 4) {
            float2 xlo[4], xhi[4];
            #pragma unroll
            for (int cc = 0; cc < 4; cc++) {
                float4 xv = *(const float4*)&xT[(c0 + cc) * PSTR + j0];
                xlo[cc] = make_float2(xv.x, xv.y);
                xhi[cc] = make_float2(xv.z, xv.w);
            }
            #pragma unroll
            for (int a = 0; a < 8; a++) {
                float4 wv = *(const float4*)&wbase[a * 96 + c0];
                #pragma unroll
                for (int cc = 0; cc < 4; cc++) {
                    float wsc = fcomp(wv, cc);
                    float2 w2 = make_float2(wsc, wsc);
                    acc[a][0] = ffma2(w2, xlo[cc], acc[a][0]);
                    acc[a][1] = ffma2(w2, xhi[cc], acc[a][1]);
                }
            }
        }

        const float s = (r0 < 96) ? SCALE : 1.f;
        float* pgw = Pg + (size_t)w * 288 * PSTR;
        #pragma unroll
        for (int a = 0; a < 8; a++) {
            float4 o = make_float4(acc[a][0].x * s, acc[a][0].y * s,
                                   acc[a][1].x * s, acc[a][1].y * s);
            *(float4*)&pgw[(r0 + a) * PSTR + j0] = o;
        }
    }
}

// ================= K2: per (window, head) attention =================
// grid = 3*BW, block = 256
__global__ __launch_bounds__(256, 2)
void k2_attn(const float* __restrict__ mask, const float* __restrict__ Bw, int nW)
{
    __shared__ float QK[96 * PSTR];   // rows 0..31 Q[e][i], 32..63 K[e][j], 64..95 Y[e][j]
    __shared__ float Ss[52 * PSTR];   // S[i][j], rows 49..51 zero
    const int bid = blockIdx.x;
    const int w   = bid / NH;
    const int h   = bid - w * NH;
    const int tid = threadIdx.x;
    const float* pgw = Pg + (size_t)w * 288 * PSTR;

    // stage Q/K/Y head slices (96 rows x 13 float4)
    for (int i = tid; i < 96 * 13; i += 256) {
        int m = i / 13, f = (i - m * 13) * 4;
        int r = (m < 32) ? (h * 32 + m)
              : (m < 64) ? (96 + h * 32 + (m - 32))
                         : (192 + h * 32 + (m - 64));
        *(float4*)&QK[m * PSTR + f] = *(const float4*)&pgw[r * PSTR + f];
    }
    if (tid < 3 * 13) {               // zero S pad rows 49..51
        int rr = 49 + tid / 13, f = (tid % 13) * 4;
        *(float4*)&Ss[rr * PSTR + f] = make_float4(0.f, 0.f, 0.f, 0.f);
    }
    __syncthreads();

    // logits 4i x 4j tiles (169)
    if (tid < 169) {
        const int it = tid / 13;
        const int jt = tid - it * 13;
        const int i0 = it * 4;
        const int j0 = jt * 4;
        const float* qb = QK + i0;
        const float* kb = QK + 32 * PSTR + j0;

        float2 acc[4][2];
        #pragma unroll
        for (int ii = 0; ii < 4; ii++) {
            acc[ii][0] = make_float2(0.f, 0.f);
            acc[ii][1] = make_float2(0.f, 0.f);
        }
        #pragma unroll 4
        for (int e = 0; e < 32; e++) {
            float4 qv = *(const float4*)&qb[e * PSTR];
            float4 kv = *(const float4*)&kb[e * PSTR];
            float2 kp0 = make_float2(kv.x, kv.y);
            float2 kp1 = make_float2(kv.z, kv.w);
            #pragma unroll
            for (int ii = 0; ii < 4; ii++) {
                float q = fcomp(qv, ii);
                float2 q2 = make_float2(q, q);
                acc[ii][0] = ffma2(q2, kp0, acc[ii][0]);
                acc[ii][1] = ffma2(q2, kp1, acc[ii][1]);
            }
        }
        const float* biash = gBias + h * (K2T * K2T);
        const float* maskb = mask + (size_t)(w % nW) * (K2T * K2T);
        #pragma unroll
        for (int ii = 0; ii < 4; ii++) {
            int i = i0 + ii;
            if (i < K2T) {
                float* srow = Ss + i * PSTR;
                float av[4] = { acc[ii][0].x, acc[ii][0].y, acc[ii][1].x, acc[ii][1].y };
                #pragma unroll
                for (int jj = 0; jj < 4; jj++) {
                    int j = j0 + jj;
                    float v = av[jj];
                    if (j < K2T) {
                        int idx = i * K2T + j;
                        v += biash[idx] + maskb[idx];
                    }
                    srow[j] = v;
                }
            }
        }
    }
    __syncthreads();

    // softmax, warp per row (8 warps)
    {
        int warp = tid >> 5, lane = tid & 31;
        for (int row = warp; row < K2T; row += 8) {
            float* srow = Ss + row * PSTR;
            float v0 = srow[lane];
            float v1 = (lane < 17) ? srow[32 + lane] : -1e30f;
            float m = fmaxf(v0, v1);
            #pragma unroll
            for (int o = 16; o; o >>= 1) m = fmaxf(m, __shfl_xor_sync(~0u, m, o));
            float e0 = __expf(v0 - m);
            float e1 = (lane < 17) ? __expf(v1 - m) : 0.f;
            float sum = e0 + e1;
            #pragma unroll
            for (int o = 16; o; o >>= 1) sum += __shfl_xor_sync(~0u, sum, o);
            float inv = __fdividef(1.f, sum);
            srow[lane] = e0 * inv;
            if (lane < 17) srow[32 + lane] = e1 * inv;
        }
    }
    __syncthreads();

    // S@Y + bott/vbias, 4i x 4e tiles (104)
    if (tid < 104) {
        const int et = tid / 13;
        const int it = tid - et * 13;
        const int i0 = it * 4;
        const int e0 = et * 4;
        const float* sbase = Ss + i0 * PSTR;
        const float* ybase = QK + (64 + e0) * PSTR;

        float2 acc[4][4];
        #pragma unroll
        for (int ii = 0; ii < 4; ii++)
            #pragma unroll
            for (int ee = 0; ee < 4; ee++) acc[ii][ee] = make_float2(0.f, 0.f);

        #pragma unroll 2
        for (int j0 = 0; j0 < PSTR; j0 += 4) {
            float2 sp[4][2], yp[4][2];
            #pragma unroll
            for (int ii = 0; ii < 4; ii++) {
                float4 sv = *(const float4*)&sbase[ii * PSTR + j0];
                sp[ii][0] = make_float2(sv.x, sv.y);
                sp[ii][1] = make_float2(sv.z, sv.w);
            }
            #pragma unroll
            for (int ee = 0; ee < 4; ee++) {
                float4 yv = *(const float4*)&ybase[ee * PSTR + j0];
                yp[ee][0] = make_float2(yv.x, yv.y);
                yp[ee][1] = make_float2(yv.z, yv.w);
            }
            #pragma unroll
            for (int ii = 0; ii < 4; ii++)
                #pragma unroll
                for (int ee = 0; ee < 4; ee++) {
                    acc[ii][ee] = ffma2(sp[ii][0], yp[ee][0], acc[ii][ee]);
                    acc[ii][ee] = ffma2(sp[ii][1], yp[ee][1], acc[ii][ee]);
                }
        }

        float bt[4];
        #pragma unroll
        for (int ii = 0; ii < 4; ii++) bt[ii] = bottg[w * 64 + i0 + ii];
        #pragma unroll
        for (int ee = 0; ee < 4; ee++) {
            float bw = Bw[h * 32 + e0 + ee];
            float4 o = make_float4(bt[0] * (acc[0][ee].x + acc[0][ee].y + bw),
                                   bt[1] * (acc[1][ee].x + acc[1][ee].y + bw),
                                   bt[2] * (acc[2][ee].x + acc[2][ee].y + bw),
                                   bt[3] * (acc[3][ee].x + acc[3][ee].y + bw));
            *(float4*)&VTg[((size_t)w * 96 + h * 32 + e0 + ee) * PSTR + i0] = o;
        }
    }
}

// ================= K3: output projection =================
// grid = BW, block = 320
__global__ __launch_bounds__(320, 2)
void k3_out(const float* __restrict__ pw, const float* __restrict__ pb,
            float* __restrict__ out)
{
    __shared__ float VTs[DIMC * PSTR];   // VT[he][i]
    const int w   = blockIdx.x;
    const int tid = threadIdx.x;
    const float* vg = VTg + (size_t)w * DIMC * PSTR;

    for (int i = tid; i < 96 * 13; i += 320) {
        int m = i / 13, f = (i - m * 13) * 4;
        *(float4*)&VTs[m * PSTR + f] = *(const float4*)&vg[m * PSTR + f];
    }
    __syncthreads();

    float* og = out + (size_t)w * (K2T * DIMC);
    if (tid < 312) {                      // 24 d-tiles x 13 i-tiles
        const int dt = tid / 13;
        const int it = tid - dt * 13;
        const int d0 = dt * 4;
        const int i0 = it * 4;

        float2 acc[2][4];   // 2 i-pairs x 4 d
        #pragma unroll
        for (int dd = 0; dd < 4; dd++) {
            float bv = pb[d0 + dd];
            acc[0][dd] = make_float2(bv, bv);
            acc[1][dd] = make_float2(bv, bv);
        }

        #pragma unroll 2
        for (int c0 = 0; c0 < DIMC; c0 += 4) {
            float2 vlo[4], vhi[4];
            #pragma unroll
            for (int cc = 0; cc < 4; cc++) {
                float4 vv = *(const float4*)&VTs[(c0 + cc) * PSTR + i0];
                vlo[cc] = make_float2(vv.x, vv.y);
                vhi[cc] = make_float2(vv.z, vv.w);
            }
            #pragma unroll
            for (int dd = 0; dd < 4; dd++) {
                float4 wv = *(const float4*)&pw[(d0 + dd) * 96 + c0];
                #pragma unroll
                for (int cc = 0; cc < 4; cc++) {
                    float wsc = fcomp(wv, cc);
                    float2 w2 = make_float2(wsc, wsc);
                    acc[0][dd] = ffma2(w2, vlo[cc], acc[0][dd]);
                    acc[1][dd] = ffma2(w2, vhi[cc], acc[1][dd]);
                }
            }
        }

        #pragma unroll
        for (int ip = 0; ip < 2; ip++) {
            #pragma unroll
            for (int half = 0; half < 2; half++) {
                int i = i0 + ip * 2 + half;
                if (i < K2T) {
                    float4 o = (half == 0)
                        ? make_float4(acc[ip][0].x, acc[ip][1].x, acc[ip][2].x, acc[ip][3].x)
                        : make_float4(acc[ip][0].y, acc[ip][1].y, acc[ip][2].y, acc[ip][3].y);
                    *(float4*)&og[i * DIMC + d0] = o;
                }
            }
        }
    }
}

extern "C" void kernel_launch(void* const* d_in, const int* in_sizes, int n_in,
                              void* d_out, int out_size) {
    const float* x    = (const float*)d_in[0];
    const float* mask = (const float*)d_in[1];
    const float* qk_w = (const float*)d_in[2];
    const float* qk_b = (const float*)d_in[3];
    const float* rpb  = (const float*)d_in[4];
    const float* botw = (const float*)d_in[5];
    const float* botb = (const float*)d_in[6];
    const float* Gw   = (const float*)d_in[7];
    const float* Bw   = (const float*)d_in[8];
    const float* pw   = (const float*)d_in[9];
    const float* pb   = (const float*)d_in[10];
    const int*   rp   = (const int*)d_in[11];

    const int BW = in_sizes[0] / (K2T * DIMC);   // 128
    const int nW = in_sizes[1] / (K2T * K2T);    // 64

    prep_kernel<<<(DIMC * DIMC + 255) / 256, 256>>>(Gw, rpb, rp);
    k1_proj<<<2 * BW, 256>>>(x, qk_w, qk_b, botw, botb);
    k2_attn<<<NH * BW, 256>>>(mask, Bw, nW);
    k3_out<<<BW, 320>>>(pw, pb, (float*)d_out);
}